// round 4
// baseline (speedup 1.0000x reference)
#include <cuda_runtime.h>
#include <cstdint>
#include <cstddef>

#define NB 64
#define NH 12
#define NP 197
#define ND 64
#define TOPK 10
#define FULLMASK 0xffffffffu
#define NSL 13          // elements per lane (16-lane group covers 208 >= 197)
#define LENT 11         // smem list entries/lane: [2..7] real, [8..10] zero sentinels

// Persistent device state (statically initialized; last block resets -> replay-safe)
__device__ double g_acc = 0.0;
__device__ unsigned g_done = 0;

// descending compare-exchange (2x IMNMX.U32)
__device__ __forceinline__ void ceu(unsigned& a, unsigned& b) {
    unsigned mx = a > b ? a : b;
    unsigned mn = a > b ? b : a;
    a = mx; b = mn;
}

// Batcher odd-even mergesort, n=8, 19 CE (two sort4 + odd-even merge).
__device__ __forceinline__ void sort8d(unsigned* s) {
    ceu(s[0],s[1]); ceu(s[2],s[3]); ceu(s[4],s[5]); ceu(s[6],s[7]);
    ceu(s[0],s[2]); ceu(s[1],s[3]); ceu(s[4],s[6]); ceu(s[5],s[7]);
    ceu(s[1],s[2]); ceu(s[5],s[6]);
    ceu(s[0],s[4]); ceu(s[1],s[5]); ceu(s[2],s[6]); ceu(s[3],s[7]);
    ceu(s[2],s[4]); ceu(s[3],s[5]);
    ceu(s[1],s[2]); ceu(s[3],s[4]); ceu(s[5],s[6]);
}
// Knuth 9-CE sorting network for n=5.
__device__ __forceinline__ void sort5d(unsigned* s) {
    ceu(s[0],s[1]); ceu(s[3],s[4]);
    ceu(s[2],s[4]);
    ceu(s[2],s[3]); ceu(s[1],s[4]);
    ceu(s[0],s[3]);
    ceu(s[0],s[2]); ceu(s[1],s[3]);
    ceu(s[1],s[2]);
}
// a[0..7] desc, b[0..4] desc  ->  a[0..7] = sorted top-8 of the 13.
// (a, reverse(b) padded with -inf) is bitonic; half-cleaner keeps the top half
// (5 max ops; a[0..2] pair with -inf), which is bitonic -> 12-CE bitonic merge.
__device__ __forceinline__ void top8_merge(unsigned* a, const unsigned* b) {
    a[3] = max(a[3], b[4]); a[4] = max(a[4], b[3]);
    a[5] = max(a[5], b[2]); a[6] = max(a[6], b[1]); a[7] = max(a[7], b[0]);
    ceu(a[0],a[4]); ceu(a[1],a[5]); ceu(a[2],a[6]); ceu(a[3],a[7]);
    ceu(a[0],a[2]); ceu(a[1],a[3]); ceu(a[4],a[6]); ceu(a[5],a[7]);
    ceu(a[0],a[1]); ceu(a[2],a[3]); ceu(a[4],a[5]); ceu(a[6],a[7]);
}

__device__ __forceinline__ void load13(float* y, const float* __restrict__ row, int hl) {
#pragma unroll
    for (int k = 0; k < 12; ++k) y[k] = row[k * 16 + hl];
    y[12] = (hl < NP - 192) ? row[192 + hl] : 0.f;    // guard tensor-end OOB
}

__global__ void __launch_bounds__(256, 2)
hintop_main(const float* __restrict__ att_s, const float* __restrict__ att_t,
            const float* __restrict__ v_s,   const float* __restrict__ v_t,
            float* __restrict__ out) {
    extern __shared__ float smem[];
    float* vsS = smem;                              // NP*ND f32
    float* vsT = smem + NP * ND;
    unsigned* lists = reinterpret_cast<unsigned*>(smem + 2 * NP * ND); // 8*LENT*32 u32

    const int bh   = blockIdx.x;
    const int warp = threadIdx.x >> 5;
    const int lane = threadIdx.x & 31;
    const int hl   = lane & 15;                     // lane within half-group
    const bool isS = (lane < 16);

    {   // fill both v tiles (f32)
        const float4* a4 = reinterpret_cast<const float4*>(v_s + (size_t)bh * NP * ND);
        const float4* b4 = reinterpret_cast<const float4*>(v_t + (size_t)bh * NP * ND);
        float4* s4 = reinterpret_cast<float4*>(vsS);
        float4* t4 = reinterpret_cast<float4*>(vsT);
        for (int i = threadIdx.x; i < NP * ND / 4; i += 256) {
            s4[i] = a4[i];
            t4[i] = b4[i];
        }
    }

    // per-lane private sorted-list slots: base word index; sentinels written once
    const int lbase = warp * (LENT * 32) + lane;
    lists[lbase + 8 * 32]  = 0u;
    lists[lbase + 9 * 32]  = 0u;
    lists[lbase + 10 * 32] = 0u;
    __syncthreads();

    // this lane's att tensor (S for lanes 0-15, T for 16-31) and v tile
    const float* __restrict__ arow = (isS ? att_s : att_t) + (size_t)bh * NP * NP;
    const float* __restrict__ vt   = isS ? vsS : vsT;
    const unsigned gmask = isS ? 0x0000FFFFu : 0xFFFF0000u;

    float lsum = 0.f;
    int p = warp;
    float cy[NSL], ny[NSL];
    if (p < NP) load13(cy, arow + (size_t)p * NP, hl);

    while (p < NP) {
        const int pn = p + 8;

        // ---- build keys: positive float bits (order = bit order), idx in low 8
        unsigned a[8], b[5];
#pragma unroll
        for (int k = 0; k < NSL; ++k) {
            float f = fmaxf(cy[k], -15.f) + 16.f;            // f in [1, ~22] > 0
            unsigned key = (__float_as_uint(f) & 0xFFFFFF00u) | (unsigned)(k * 16 + hl);
            if (k < 8) a[k] = key; else b[k - 8] = key;
        }
        if (hl >= NP - 192) b[4] = 0u;                       // invalid tail slot

        sort8d(a);
        sort5d(b);
        top8_merge(a, b);                                    // a = sorted top-8

        // spill entries 2..7 to smem list (entry1 stays in reg as 'nextv')
#pragma unroll
        for (int e = 2; e < 8; ++e) lists[lbase + e * 32] = a[e];

        // ---- prefetch next row (clamped; discarded on exit)
        {
            int pl = pn < NP - 1 ? pn : NP - 1;
            load13(ny, arow + (size_t)pl * NP, hl);
        }

        // ---- pop warp-group top-10; speculative one-ahead list read
        unsigned cand = a[0];
        unsigned nextv = a[1];
        int lptr = lbase + 2 * 32;
        float ac0 = 0.f, ac1 = 0.f, ac2 = 0.f, ac3 = 0.f, wsum = 0.f;
#pragma unroll
        for (int it = 0; it < TOPK; ++it) {
            unsigned wm = __reduce_max_sync(gmask, cand);    // group max (keys unique)
            if (it < TOPK - 1) {
                bool own = (cand == wm);
                cand = own ? nextv : cand;                   // expose next sorted elem
                if (own) {                                   // refill off critical path
                    nextv = lists[lptr];
                    lptr += 32;
                }
            }
            float yv = __uint_as_float(wm & 0xFFFFFF00u) - 16.f;
            float w  = __expf(yv);                           // normalizer cancels shift
            unsigned e = wm & 0xFFu;                         // element/v-row index
            const float4 vv = *reinterpret_cast<const float4*>(vt + e * ND + (hl << 2));
            ac0 = fmaf(w, vv.x, ac0);
            ac1 = fmaf(w, vv.y, ac1);
            ac2 = fmaf(w, vv.z, ac2);
            ac3 = fmaf(w, vv.w, ac3);
            wsum += w;
        }

        // ---- normalize, cross-half diff, accumulate MSE partial
        float inv = __fdividef(1.f, wsum);
        float o0 = ac0 * inv, o1 = ac1 * inv, o2 = ac2 * inv, o3 = ac3 * inv;
        float d0 = o0 - __shfl_down_sync(FULLMASK, o0, 16);  // upper lanes: d = 0
        float d1 = o1 - __shfl_down_sync(FULLMASK, o1, 16);
        float d2 = o2 - __shfl_down_sync(FULLMASK, o2, 16);
        float d3 = o3 - __shfl_down_sync(FULLMASK, o3, 16);
        lsum = fmaf(d0, d0, lsum);
        lsum = fmaf(d1, d1, lsum);
        lsum = fmaf(d2, d2, lsum);
        lsum = fmaf(d3, d3, lsum);

        p = pn;
#pragma unroll
        for (int k = 0; k < NSL; ++k) cy[k] = ny[k];
    }

    // warp reduce -> block reduce -> one double atomic; last block finalizes.
#pragma unroll
    for (int off = 16; off; off >>= 1) lsum += __shfl_xor_sync(FULLMASK, lsum, off);

    __shared__ float wsum_sh[8];
    if ((threadIdx.x & 31) == 0) wsum_sh[warp] = lsum;
    __syncthreads();
    if (threadIdx.x == 0) {
        float t = 0.f;
#pragma unroll
        for (int w = 0; w < 8; ++w) t += wsum_sh[w];
        atomicAdd(&g_acc, (double)t);
        __threadfence();
        unsigned ticket = atomicAdd(&g_done, 1);
        if (ticket == (unsigned)(gridDim.x - 1)) {
            __threadfence();
            double total = atomicAdd(&g_acc, 0.0);
            out[0] = (float)(total / (double)((size_t)NB * NH * NP * ND));
            g_acc = 0.0;                                     // reset for graph replay
            g_done = 0;
            __threadfence();
        }
    }
}

extern "C" void kernel_launch(void* const* d_in, const int* in_sizes, int n_in,
                              void* d_out, int out_size) {
    const float* att_s = (const float*)d_in[0];
    const float* att_t = (const float*)d_in[1];
    const float* v_s   = (const float*)d_in[2];
    const float* v_t   = (const float*)d_in[3];

    const int smem_bytes = 2 * NP * ND * 4 + 8 * LENT * 32 * 4;   // 112,128 B
    cudaFuncSetAttribute(hintop_main, cudaFuncAttributeMaxDynamicSharedMemorySize,
                         smem_bytes);

    hintop_main<<<NB * NH, 256, smem_bytes>>>(att_s, att_t, v_s, v_t, (float*)d_out);
}

// round 5
// speedup vs baseline: 1.4458x; 1.4458x over previous
#include <cuda_runtime.h>
#include <cstdint>
#include <cstddef>

#define NB 64
#define NH 12
#define NP 197
#define ND 64
#define TOPK 10
#define NSLOT 7
#define FULLMASK 0xffffffffu
#define LSLOTS 12    // per-warp per-lane list slots: S e2..e6 in 0..4, sentinels 5..6, T e2..e6 in 11..7

// Persistent device state (statically initialized; last block resets -> replay-safe)
__device__ double g_acc = 0.0;
__device__ unsigned g_done = 0;

// descending compare-exchange (2x IMNMX.U32)
__device__ __forceinline__ void ceu(unsigned& a, unsigned& b) {
    unsigned mx = a > b ? a : b;
    unsigned mn = a > b ? b : a;
    a = mx; b = mn;
}
// Batcher odd-even mergesort for 8 with element 7 = const-min -> 16-CE sort-7.
__device__ __forceinline__ void sort7(unsigned* s) {
    ceu(s[0],s[1]); ceu(s[2],s[3]); ceu(s[4],s[5]);
    ceu(s[0],s[2]); ceu(s[1],s[3]); ceu(s[4],s[6]);
    ceu(s[1],s[2]); ceu(s[5],s[6]);
    ceu(s[0],s[4]); ceu(s[1],s[5]); ceu(s[2],s[6]);
    ceu(s[2],s[4]); ceu(s[3],s[5]);
    ceu(s[1],s[2]); ceu(s[3],s[4]); ceu(s[5],s[6]);
}

// Load one att row: 7 slots/lane. Pad -> shifted key 0.25, below any real key.
__device__ __forceinline__ void load_row(float* y, const float* __restrict__ row,
                                         int lane) {
#pragma unroll
    for (int k = 0; k < 6; ++k) y[k] = row[k * 32 + lane];
    y[6] = (lane < NP - 192) ? row[192 + lane] : -15.75f;
}

__global__ void __launch_bounds__(256, 2)
hintop_main(const float* __restrict__ att_s, const float* __restrict__ att_t,
            const float* __restrict__ v_s,   const float* __restrict__ v_t,
            float* __restrict__ out) {
    extern __shared__ float smem[];
    float* vsS = smem;                                   // NP*ND f32 each
    float* vsT = smem + NP * ND;
    unsigned* lists = reinterpret_cast<unsigned*>(smem + 2 * NP * ND);

    const int bh   = blockIdx.x;
    const int warp = threadIdx.x >> 5;
    const int lane = threadIdx.x & 31;

    {   // fill both v tiles (f32, vectorized)
        const float4* a4 = reinterpret_cast<const float4*>(v_s + (size_t)bh * NP * ND);
        const float4* b4 = reinterpret_cast<const float4*>(v_t + (size_t)bh * NP * ND);
        float4* s4 = reinterpret_cast<float4*>(vsS);
        float4* t4 = reinterpret_cast<float4*>(vsT);
        for (int i = threadIdx.x; i < NP * ND / 4; i += 256) {
            s4[i] = a4[i];
            t4[i] = b4[i];
        }
    }
    // per-warp per-lane list base; zero the two shared sentinel slots once
    const int lb = warp * (LSLOTS * 32) + lane;
    lists[lb + 5 * 32] = 0u;
    lists[lb + 6 * 32] = 0u;
    __syncthreads();

    const float* aS = att_s + (size_t)bh * NP * NP;
    const float* aT = att_t + (size_t)bh * NP * NP;
    const float2* __restrict__ v2S = reinterpret_cast<const float2*>(vsS) + lane;
    const float2* __restrict__ v2T = reinterpret_cast<const float2*>(vsT) + lane;

    float lsum = 0.f;
    int p = warp;
    float cS[NSLOT], cT[NSLOT], nS[NSLOT], nT[NSLOT];
    if (p < NP) {
        load_row(cS, aS + (size_t)p * NP, lane);
        load_row(cT, aT + (size_t)p * NP, lane);
    }

    while (p < NP) {
        const int pn = p + 8;

        // ---- keys: f = y+16 > 0 (bit order == value order), idx in low 8 bits
        unsigned sS[NSLOT], sT[NSLOT];
#pragma unroll
        for (int k = 0; k < NSLOT; ++k) {
            unsigned idx = (unsigned)(k * 32 + lane);
            sS[k] = (__float_as_uint(cS[k] + 16.f) & 0xFFFFFF00u) | idx;
            sT[k] = (__float_as_uint(cT[k] + 16.f) & 0xFFFFFF00u) | idx;
        }
        sort7(sS);
        sort7(sT);

        // ---- spill entries 2..6; S ascending slots 0..4, T descending 11..7
#pragma unroll
        for (int j = 0; j < 5; ++j) {
            lists[lb + j * 32] = sS[2 + j];
            lists[lb + (11 - j) * 32] = sT[2 + j];
        }

        // ---- prefetch next row pair (clamped; discarded at loop exit)
        {
            int pl = pn < NP - 1 ? pn : NP - 1;
            load_row(nS, aS + (size_t)pl * NP, lane);
            load_row(nT, aT + (size_t)pl * NP, lane);
        }

        // ---- pop top-10 per chain; two independent REDUX chains for ILP
        unsigned candS = sS[0], nextS = sS[1];
        unsigned candT = sT[0], nextT = sT[1];
        int lpS = lb;                 // reads slots 0..4 then sentinels 5,6
        int lpT = lb + 11 * 32;       // reads slots 11..7 then sentinels 6,5
        float2 accS = make_float2(0.f, 0.f), accT = make_float2(0.f, 0.f);
        float wsS = 0.f, wsT = 0.f;
#pragma unroll
        for (int it = 0; it < TOPK; ++it) {
            unsigned wmS = __reduce_max_sync(FULLMASK, candS);
            unsigned wmT = __reduce_max_sync(FULLMASK, candT);

            if (it < TOPK - 1) {
                bool oS = (candS == wmS);         // unique keys -> one owner
                candS = oS ? nextS : candS;
                if (oS) { nextS = lists[lpS]; lpS += 32; }   // refill off-chain
                bool oT = (candT == wmT);
                candT = oT ? nextT : candT;
                if (oT) { nextT = lists[lpT]; lpT -= 32; }
            }

            // weight: exp(y+16); the +16 cancels in the normalizer
            float wS = __expf(__uint_as_float(wmS & 0xFFFFFF00u));
            float wT = __expf(__uint_as_float(wmT & 0xFFFFFF00u));
            unsigned iS = wmS & 0xFFu;
            unsigned iT = wmT & 0xFFu;
            float2 vvS = v2S[iS * 32];
            float2 vvT = v2T[iT * 32];
            accS.x = fmaf(wS, vvS.x, accS.x);
            accS.y = fmaf(wS, vvS.y, accS.y);
            wsS += wS;
            accT.x = fmaf(wT, vvT.x, accT.x);
            accT.y = fmaf(wT, vvT.y, accT.y);
            wsT += wT;
        }

        float invS = __fdividef(1.0f, wsS);
        float invT = __fdividef(1.0f, wsT);
        float dx = accS.x * invS - accT.x * invT;
        float dy = accS.y * invS - accT.y * invT;
        lsum = fmaf(dx, dx, lsum);
        lsum = fmaf(dy, dy, lsum);

        p = pn;
#pragma unroll
        for (int k = 0; k < NSLOT; ++k) { cS[k] = nS[k]; cT[k] = nT[k]; }
    }

    // warp reduce -> block reduce -> one double atomic; last block finalizes.
#pragma unroll
    for (int off = 16; off; off >>= 1) lsum += __shfl_xor_sync(FULLMASK, lsum, off);

    __shared__ float wsum_sh[8];
    if (lane == 0) wsum_sh[warp] = lsum;
    __syncthreads();
    if (threadIdx.x == 0) {
        float t = 0.f;
#pragma unroll
        for (int w = 0; w < 8; ++w) t += wsum_sh[w];
        atomicAdd(&g_acc, (double)t);
        __threadfence();
        unsigned ticket = atomicAdd(&g_done, 1);
        if (ticket == (unsigned)(gridDim.x - 1)) {
            __threadfence();
            double total = atomicAdd(&g_acc, 0.0);
            out[0] = (float)(total / (double)((size_t)NB * NH * NP * ND));
            g_acc = 0.0;                                 // reset for graph replay
            g_done = 0;
            __threadfence();
        }
    }
}

extern "C" void kernel_launch(void* const* d_in, const int* in_sizes, int n_in,
                              void* d_out, int out_size) {
    const float* att_s = (const float*)d_in[0];
    const float* att_t = (const float*)d_in[1];
    const float* v_s   = (const float*)d_in[2];
    const float* v_t   = (const float*)d_in[3];

    const int smem_bytes = 2 * NP * ND * 4 + 8 * LSLOTS * 32 * 4;   // 113,152 B
    cudaFuncSetAttribute(hintop_main, cudaFuncAttributeMaxDynamicSharedMemorySize,
                         smem_bytes);

    hintop_main<<<NB * NH, 256, smem_bytes>>>(att_s, att_t, v_s, v_t, (float*)d_out);
}